// round 8
// baseline (speedup 1.0000x reference)
#include <cuda_runtime.h>
#include <cuda_fp16.h>
#include <cuda_bf16.h>

#define N_NODES 100000
#define D_DIM   64
#define E_EDGES 1600000

#define SCAN_BLOCK 1024
#define N_SCAN_BLOCKS ((N_NODES + SCAN_BLOCK - 1) / SCAN_BLOCK)   // 98

// ---- device scratch (no cudaMalloc allowed; zero-initialized at load) ----
__device__ float  g_adst[N_NODES];          // h[i].w_dst + bias
__device__ float2 g_spack[N_NODES];         // (h[i].w_src, dnorm[i])
__device__ int    g_counts[N_NODES];        // in-degree histogram
                                            // INVARIANT: zero on kernel_launch entry
                                            // (re-zeroed by scan kernel each call)
__device__ int    g_offsets[N_NODES + 1];   // CSR row offsets
__device__ int    g_rank[E_EDGES];          // edge rank within its dst bucket
__device__ unsigned long long g_scanstate[N_SCAN_BLOCKS]; // {status:32, value:32}
                                            // zeroed by hist kernel each call
__device__ int    g_edge_src[E_EDGES];      // CSR column (src node) list
__device__ __half g_hhalf[N_NODES * D_DIM]; // fp16 mirror of h

__device__ __forceinline__ float fast_tanh(float x) {
    float r;
    asm("tanh.approx.f32 %0, %1;" : "=f"(r) : "f"(x));
    return r;
}

// ---------------------------------------------------------------------------
// K1: histogram + rank. One thread per edge. Also zeroes lookback state.
// ---------------------------------------------------------------------------
__global__ void hist_kernel(const int* __restrict__ dst)
{
    int e = blockIdx.x * blockDim.x + threadIdx.x;
    if (e < N_SCAN_BLOCKS) g_scanstate[e] = 0ull;
    if (e >= E_EDGES) return;
    g_rank[e] = atomicAdd(&g_counts[dst[e]], 1);
}

// ---------------------------------------------------------------------------
// K2: fused single-pass scan (decoupled lookback) + node dots + fp16 mirror.
// 98 blocks x 1024 threads, all resident simultaneously (148 SMs) => safe.
// Scan part first (publish fast), node work after (hides lookback drain).
// ---------------------------------------------------------------------------
__global__ void scan_nodes_kernel(const float* __restrict__ h,
                                  const float* __restrict__ dnorm,
                                  const float* __restrict__ gate_w,
                                  const float* __restrict__ gate_b)
{
    __shared__ int sdata[SCAN_BLOCK];
    __shared__ int s_base;

    int tid = threadIdx.x;
    int b   = blockIdx.x;
    int i   = b * SCAN_BLOCK + tid;

    int v = (i < N_NODES) ? g_counts[i] : 0;
    if (i < N_NODES) g_counts[i] = 0;          // restore invariant for next replay
    sdata[tid] = v;
    __syncthreads();

    #pragma unroll
    for (int off = 1; off < SCAN_BLOCK; off <<= 1) {
        int t = (tid >= off) ? sdata[tid - off] : 0;
        __syncthreads();
        sdata[tid] += t;
        __syncthreads();
    }
    int total = sdata[SCAN_BLOCK - 1];

    if (tid == 0) {
        if (b == 0) {
            atomicExch(&g_scanstate[0], (2ull << 32) | (unsigned int)total);
            s_base = 0;
        } else {
            // publish aggregate
            atomicExch(&g_scanstate[b], (1ull << 32) | (unsigned int)total);
            // lookback
            int base = 0;
            int p = b - 1;
            while (true) {
                unsigned long long st = atomicAdd(&g_scanstate[p], 0ull);
                unsigned int status = (unsigned int)(st >> 32);
                if (status == 0) continue;                 // not ready, spin
                base += (int)(unsigned int)(st & 0xFFFFFFFFull);
                if (status == 2) break;                    // prefix: done
                p--;                                       // aggregate: keep going
            }
            atomicExch(&g_scanstate[b], (2ull << 32) | (unsigned int)(base + total));
            s_base = base;
        }
    }
    __syncthreads();

    int base = s_base;
    if (i < N_NODES) g_offsets[i] = base + sdata[tid] - v;   // exclusive
    if (b == 0 && tid == 0) g_offsets[N_NODES] = E_EDGES;

    // ---- node dots + fp16 mirror: this block handles nodes [b*1024, +1024) ----
    int warp = tid >> 5;
    int lane = tid & 31;

    float2 wd = *reinterpret_cast<const float2*>(gate_w + lane * 2);
    float2 ws = *reinterpret_cast<const float2*>(gate_w + D_DIM + lane * 2);
    float bias = gate_b[0];

    int node_base = b * SCAN_BLOCK + warp * 32;
    #pragma unroll 4
    for (int k = 0; k < 32; k++) {
        int node = node_base + k;
        if (node >= N_NODES) break;

        float2 hv = *reinterpret_cast<const float2*>(h + (long long)node * D_DIM + lane * 2);

        *reinterpret_cast<__half2*>(g_hhalf + (long long)node * D_DIM + lane * 2) =
            __floats2half2_rn(hv.x, hv.y);

        float pd = hv.x * wd.x + hv.y * wd.y;
        float ps = hv.x * ws.x + hv.y * ws.y;

        #pragma unroll
        for (int off = 16; off > 0; off >>= 1) {
            pd += __shfl_xor_sync(0xFFFFFFFFu, pd, off);
            ps += __shfl_xor_sync(0xFFFFFFFFu, ps, off);
        }

        if (lane == 0) {
            g_adst[node]  = pd + bias;
            g_spack[node] = make_float2(ps, dnorm[node]);
        }
    }
}

// ---------------------------------------------------------------------------
// K3: ATOMIC-FREE CSR scatter. pos = offsets[dst[e]] + rank[e].
// ---------------------------------------------------------------------------
__global__ void csr_scatter_kernel(const int* __restrict__ src,
                                   const int* __restrict__ dst)
{
    int t = blockIdx.x * blockDim.x + threadIdx.x;
    if (t >= E_EDGES / 4) return;

    int4 s4 = reinterpret_cast<const int4*>(src)[t];
    int4 d4 = reinterpret_cast<const int4*>(dst)[t];
    int4 r4 = reinterpret_cast<const int4*>(g_rank)[t];

    int o0 = g_offsets[d4.x];
    int o1 = g_offsets[d4.y];
    int o2 = g_offsets[d4.z];
    int o3 = g_offsets[d4.w];

    g_edge_src[o0 + r4.x] = s4.x;
    g_edge_src[o1 + r4.y] = s4.y;
    g_edge_src[o2 + r4.z] = s4.z;
    g_edge_src[o3 + r4.w] = s4.w;
}

// ---------------------------------------------------------------------------
// K4: gather-accumulate. One warp per dst node, fp16 h rows, no atomics.
// ---------------------------------------------------------------------------
__global__ void gather_kernel(const float* __restrict__ dnorm,
                              float* __restrict__ out)
{
    int tid  = blockIdx.x * blockDim.x + threadIdx.x;
    int d    = tid >> 5;
    int lane = tid & 31;
    if (d >= N_NODES) return;

    int beg = g_offsets[d];
    int end = g_offsets[d + 1];

    float adst_d = g_adst[d];
    float dnd    = dnorm[d];

    float accx = 0.f, accy = 0.f;
    const __half* __restrict__ hh = g_hhalf;

    for (int base = beg; base < end; base += 32) {
        int idx = base + lane;
        int s = 0;
        float coef = 0.f;
        if (idx < end) {
            s = g_edge_src[idx];
            float2 sp = g_spack[s];
            coef = fast_tanh(adst_d + sp.x) * dnd * sp.y;
        }
        int cnt = end - base;
        if (cnt > 32) cnt = 32;

        int j = 0;
        for (; j + 4 <= cnt; j += 4) {
            int   s0 = __shfl_sync(0xFFFFFFFFu, s, j);
            int   s1 = __shfl_sync(0xFFFFFFFFu, s, j + 1);
            int   s2 = __shfl_sync(0xFFFFFFFFu, s, j + 2);
            int   s3 = __shfl_sync(0xFFFFFFFFu, s, j + 3);
            float c0 = __shfl_sync(0xFFFFFFFFu, coef, j);
            float c1 = __shfl_sync(0xFFFFFFFFu, coef, j + 1);
            float c2 = __shfl_sync(0xFFFFFFFFu, coef, j + 2);
            float c3 = __shfl_sync(0xFFFFFFFFu, coef, j + 3);
            __half2 a0 = *reinterpret_cast<const __half2*>(hh + (long long)s0 * D_DIM + lane * 2);
            __half2 a1 = *reinterpret_cast<const __half2*>(hh + (long long)s1 * D_DIM + lane * 2);
            __half2 a2 = *reinterpret_cast<const __half2*>(hh + (long long)s2 * D_DIM + lane * 2);
            __half2 a3 = *reinterpret_cast<const __half2*>(hh + (long long)s3 * D_DIM + lane * 2);
            float2 f0 = __half22float2(a0);
            float2 f1 = __half22float2(a1);
            float2 f2 = __half22float2(a2);
            float2 f3 = __half22float2(a3);
            accx = fmaf(c0, f0.x, accx); accy = fmaf(c0, f0.y, accy);
            accx = fmaf(c1, f1.x, accx); accy = fmaf(c1, f1.y, accy);
            accx = fmaf(c2, f2.x, accx); accy = fmaf(c2, f2.y, accy);
            accx = fmaf(c3, f3.x, accx); accy = fmaf(c3, f3.y, accy);
        }
        for (; j < cnt; j++) {
            int   sj = __shfl_sync(0xFFFFFFFFu, s, j);
            float cj = __shfl_sync(0xFFFFFFFFu, coef, j);
            __half2 av = *reinterpret_cast<const __half2*>(hh + (long long)sj * D_DIM + lane * 2);
            float2 fv = __half22float2(av);
            accx = fmaf(cj, fv.x, accx);
            accy = fmaf(cj, fv.y, accy);
        }
    }

    *reinterpret_cast<float2*>(out + (long long)d * D_DIM + lane * 2) =
        make_float2(accx, accy);
}

// ---------------------------------------------------------------------------
// Launch (4 kernels)
// ---------------------------------------------------------------------------
extern "C" void kernel_launch(void* const* d_in, const int* in_sizes, int n_in,
                              void* d_out, int out_size)
{
    const float* h      = (const float*)d_in[0];   // (N, 64)
    const float* dnorm  = (const float*)d_in[1];   // (N,)
    const float* gate_w = (const float*)d_in[2];   // (1, 128)
    const float* gate_b = (const float*)d_in[3];   // (1,)
    const int*   src    = (const int*)  d_in[4];   // (E,)
    const int*   dst    = (const int*)  d_in[5];   // (E,)
    float* out = (float*)d_out;                    // (N, 64) float32

    hist_kernel<<<(E_EDGES + 255) / 256, 256>>>(dst);
    scan_nodes_kernel<<<N_SCAN_BLOCKS, SCAN_BLOCK>>>(h, dnorm, gate_w, gate_b);
    {
        int threads = 256;
        int work = E_EDGES / 4;                    // 400000
        csr_scatter_kernel<<<(work + threads - 1) / threads, threads>>>(src, dst);
    }
    {
        long long total = (long long)N_NODES * 32;
        int blocks = (int)((total + 255) / 256);
        gather_kernel<<<blocks, 256>>>(dnorm, out);
    }
}